// round 2
// baseline (speedup 1.0000x reference)
#include <cuda_runtime.h>
#include <math.h>

// ROI align (14x14 bilinear grid) + 2x2 maxpool -> (B,N,C,7,7)
// B=4, N=512, C=256, Hf=Wf=50, IMG=800 -> fx=fy=0.0625
// Box in feature units: x,y in [0,22], w,h in [5,22] -> patch <= 22x22.

#define BB 4
#define NN 512
#define CC 256
#define HF 50
#define WF 50
#define OUTD 14
#define TC 16            // channels per tile
#define PSTRIDE 23       // padded col stride (h <= 22, odd)
#define PROWS 22

__device__ __forceinline__ void cp_async4(void* smem_dst, const void* gmem_src) {
    unsigned saddr = (unsigned)__cvta_generic_to_shared(smem_dst);
    asm volatile("cp.async.ca.shared.global [%0], [%1], 4;\n"
                 :: "r"(saddr), "l"(gmem_src));
}

__global__ __launch_bounds__(256)
void roi_align_pool_kernel(const float* __restrict__ proposals,
                           const float* __restrict__ features,
                           float* __restrict__ out)
{
    const int bn = blockIdx.x;          // b*N + n
    const int b  = bn >> 9;             // / NN

    __shared__ int    s_box[4];                 // x, y, w, h
    __shared__ int    s_rlB[OUTD], s_rhB[OUTD]; // row-low/high * PSTRIDE
    __shared__ int    s_cl[OUTD],  s_ch[OUTD];
    __shared__ float  s_rf[OUTD],  s_cf[OUTD];
    __shared__ int4   s_off[196];               // per grid point: 4 smem offsets
    __shared__ float4 s_wt[196];                // per grid point: 4 bilinear weights
    __shared__ float  patch[TC][PROWS * PSTRIDE];

    const int tid  = threadIdx.x;
    const int warp = tid >> 5;
    const int lane = tid & 31;

    if (tid < 4) {
        // fx = fy = 0.0625 exactly; trunc-cast matches astype(int32) for >=0
        s_box[tid] = (int)(proposals[bn * 4 + tid] * 0.0625f);
    }
    __syncthreads();

    const int x = s_box[0], y = s_box[1], w = s_box[2], h = s_box[3];

    if (tid < 2 * OUTD) {
        const bool  isRow = tid < OUTD;
        const int   ii    = isRow ? tid : tid - OUTD;
        const int   len   = isRow ? w : h;
        const float scale = (float)(len - 1) / 13.0f;
        const float c     = (float)ii * scale;
        const int   low   = (int)floorf(c);
        const float frac  = c - (float)low;
        const int   high  = min(low + 1, len - 1);
        if (isRow) { s_rlB[ii] = low * PSTRIDE; s_rhB[ii] = high * PSTRIDE; s_rf[ii] = frac; }
        else       { s_cl[ii]  = low;           s_ch[ii]  = high;           s_cf[ii] = frac; }
    }
    __syncthreads();

    // Precompute per-grid-point offsets + weights (196 points; thread tid < 196)
    if (tid < 196) {
        const int i = tid / 14;             // row grid index
        const int j = tid - i * 14;         // col grid index
        const int rlB = s_rlB[i], rhB = s_rhB[i];
        const int cl  = s_cl[j],  ch  = s_ch[j];
        const float rf = s_rf[i], cf = s_cf[j];
        s_off[tid] = make_int4(rlB + cl, rlB + ch, rhB + cl, rhB + ch);
        const float irf = 1.0f - rf, icf = 1.0f - cf;
        s_wt[tid] = make_float4(irf * icf, irf * cf, rf * icf, rf * cf);
    }
    // (no sync needed yet; first tile's staging below is independent, and the
    //  __syncthreads() after staging orders s_off/s_wt before compute)

    for (int c0 = 0; c0 < CC; c0 += TC) {
        // ---- stage TC channel patches via cp.async (warp per channel, lane per col)
        if (lane < h) {
            for (int ch = warp; ch < TC; ch += 8) {
                const float* src = features + ((((b * CC) + c0 + ch) * HF + x) * WF + y + lane);
                float* dst = &patch[ch][lane];
                for (int r = 0; r < w; r++) {
                    cp_async4(dst + r * PSTRIDE, src + r * WF);
                }
            }
        }
        asm volatile("cp.async.commit_group;\n" ::: "memory");
        asm volatile("cp.async.wait_group 0;\n" ::: "memory");
        __syncthreads();

        // ---- each item = one pooled output (max over 2x2 bilinear grid points)
        for (int idx = tid; idx < TC * 49; idx += 256) {
            const int tc = idx / 49;                 // const-div -> mulhi
            const int p  = idx - tc * 49;
            const int pi = p / 7;
            const int pj = p - pi * 7;
            const int g0 = (2 * pi) * 14 + 2 * pj;   // grid point index of top-left

            const float* __restrict__ pp = patch[tc];
            float m = -INFINITY;
            #pragma unroll
            for (int dg = 0; dg < 4; dg++) {
                const int g = g0 + (dg & 1) + (dg >> 1) * 14;
                const int4   o  = s_off[g];
                const float4 wt = s_wt[g];
                const float v = wt.x * pp[o.x] + wt.y * pp[o.y]
                              + wt.z * pp[o.z] + wt.w * pp[o.w];
                m = fmaxf(m, v);
            }
            out[(bn * CC + c0 + tc) * 49 + p] = m;
        }
        __syncthreads();
    }
}

extern "C" void kernel_launch(void* const* d_in, const int* in_sizes, int n_in,
                              void* d_out, int out_size)
{
    const float* proposals = (const float*)d_in[0];   // (B,N,4) f32
    const float* features  = (const float*)d_in[1];   // (B,C,Hf,Wf) f32
    float* out = (float*)d_out;                       // (B,N,C,7,7) f32
    (void)in_sizes; (void)n_in; (void)out_size;

    roi_align_pool_kernel<<<BB * NN, 256>>>(proposals, features, out);
}

// round 3
// speedup vs baseline: 2.5644x; 2.5644x over previous
#include <cuda_runtime.h>
#include <math.h>

// ROI align (14x14 bilinear grid) + 2x2 maxpool -> (B,N,C,7,7)
// B=4, N=512, C=256, Hf=Wf=50, IMG=800 -> fx=fy=0.0625
// Box in feature units: x,y in [0,22], w,h in [5,22] -> patch fits 22x22.
//
// Layout: per 16-channel tile, 4 "planes" of float4 (4 channels interleaved).
// Compute threads: tid<196, thread=(g=tid/49 channel-quad, p=tid%49 position).
// Meta (offsets/weights for the 4 bilinear grid points of p) lives in registers.

#define BB 4
#define NN 512
#define CC 256
#define HF 50
#define WF 50
#define TC 16            // channels per tile (4 planes x 4 channels)
#define PS 23            // padded row stride in positions (h <= 22)
#define PLANE 512        // float4 slots per plane (>= 21*23+22=505)

__global__ __launch_bounds__(256)
void roi_align_pool_kernel(const float* __restrict__ proposals,
                           const float* __restrict__ features,
                           float* __restrict__ out)
{
    const int bn = blockIdx.x;          // b*N + n
    const int b  = bn >> 9;

    __shared__ int   s_box[4];                    // x, y, w, h
    __shared__ int   s_rl23[14], s_rh23[14];      // row low/high * PS
    __shared__ int   s_cl[14],   s_ch[14];
    __shared__ float s_rf[14],   s_cf[14];
    __shared__ float4 planes[4 * PLANE];          // 32 KB

    const int tid  = threadIdx.x;
    const int warp = tid >> 5;
    const int lane = tid & 31;

    if (tid < 4) {
        s_box[tid] = (int)(proposals[bn * 4 + tid] * 0.0625f);
    }
    __syncthreads();

    const int x = s_box[0], y = s_box[1], w = s_box[2], h = s_box[3];

    if (tid < 28) {
        const bool  isRow = tid < 14;
        const int   ii    = isRow ? tid : tid - 14;
        const int   len   = isRow ? w : h;
        const float scale = (float)(len - 1) / 13.0f;
        const float c     = (float)ii * scale;
        const int   low   = (int)floorf(c);
        const float frac  = c - (float)low;
        const int   high  = min(low + 1, len - 1);
        if (isRow) { s_rl23[ii] = low * PS; s_rh23[ii] = high * PS; s_rf[ii] = frac; }
        else       { s_cl[ii]   = low;      s_ch[ii]   = high;      s_cf[ii] = frac; }
    }
    __syncthreads();

    // ---- per-thread meta in registers (tid < 196: g = channel quad, p = position)
    const bool active = tid < 196;
    const int  g = tid / 49;
    const int  p = tid - g * 49;
    int4   off[4];
    float4 wt[4];
    if (active) {
        const int pi = p / 7;
        const int pj = p - pi * 7;
        #pragma unroll
        for (int dg = 0; dg < 4; dg++) {
            const int i = 2 * pi + (dg >> 1);
            const int j = 2 * pj + (dg & 1);
            const int rlB = s_rl23[i], rhB = s_rh23[i];
            const int cl  = s_cl[j],   ch  = s_ch[j];
            off[dg] = make_int4(rlB + cl, rlB + ch, rhB + cl, rhB + ch);
            const float rf = s_rf[i], cf = s_cf[j];
            const float irf = 1.0f - rf, icf = 1.0f - cf;
            wt[dg] = make_float4(irf * icf, irf * cf, rf * icf, rf * cf);
        }
    }

    const float4* __restrict__ myplane = planes + g * PLANE;
    float* const outbase = out + (bn * CC) * 49 + g * 4 * 49 + p;

    const int wtasks = 4 * w;   // (plane, row) tasks
    const long fstride = (long)HF * WF;

    for (int c0 = 0; c0 < CC; c0 += TC) {
        // ---- stage: warp -> plane (warp&3), rows strided; lane = column
        for (int it = warp; it < wtasks; it += 8) {
            const int pg = it & 3;       // plane (warp&3, constant per warp)
            const int r  = it >> 2;
            if (lane < h) {
                const float* src = features
                    + (((long)(b * CC + c0 + 4 * pg) * HF + (x + r)) * WF + y + lane);
                float4 v;
                v.x = src[0];
                v.y = src[fstride];
                v.z = src[2 * fstride];
                v.w = src[3 * fstride];
                planes[pg * PLANE + r * PS + lane] = v;
            }
        }
        __syncthreads();

        // ---- compute: 4 channels per thread via float4 loads
        if (active) {
            float4 m = make_float4(-INFINITY, -INFINITY, -INFINITY, -INFINITY);
            #pragma unroll
            for (int dg = 0; dg < 4; dg++) {
                const float4 a = myplane[off[dg].x];
                const float4 bq = myplane[off[dg].y];
                const float4 c = myplane[off[dg].z];
                const float4 d = myplane[off[dg].w];
                const float4 W = wt[dg];
                float4 v;
                v.x = fmaf(W.x, a.x, fmaf(W.y, bq.x, fmaf(W.z, c.x, W.w * d.x)));
                v.y = fmaf(W.x, a.y, fmaf(W.y, bq.y, fmaf(W.z, c.y, W.w * d.y)));
                v.z = fmaf(W.x, a.z, fmaf(W.y, bq.z, fmaf(W.z, c.z, W.w * d.z)));
                v.w = fmaf(W.x, a.w, fmaf(W.y, bq.w, fmaf(W.z, c.w, W.w * d.w)));
                m.x = fmaxf(m.x, v.x);
                m.y = fmaxf(m.y, v.y);
                m.z = fmaxf(m.z, v.z);
                m.w = fmaxf(m.w, v.w);
            }
            float* o = outbase + c0 * 49;
            o[0]       = m.x;
            o[49]      = m.y;
            o[98]      = m.z;
            o[147]     = m.w;
        }
        __syncthreads();
    }
}

extern "C" void kernel_launch(void* const* d_in, const int* in_sizes, int n_in,
                              void* d_out, int out_size)
{
    const float* proposals = (const float*)d_in[0];   // (B,N,4) f32
    const float* features  = (const float*)d_in[1];   // (B,C,Hf,Wf) f32
    float* out = (float*)d_out;                       // (B,N,C,7,7) f32
    (void)in_sizes; (void)n_in; (void)out_size;

    roi_align_pool_kernel<<<BB * NN, 256>>>(proposals, features, out);
}

// round 4
// speedup vs baseline: 4.4456x; 1.7336x over previous
#include <cuda_runtime.h>
#include <cuda_fp16.h>
#include <math.h>

// ROI align (14x14 bilinear) + 2x2 maxpool -> (B,N,C,7,7)
// B=4, N=512, C=256, Hf=Wf=50, fx=fy=0.0625. Patch <= 22x22, x+w<=45, y+h<=45.
//
// Prepass: features (B,C,H,W) f32 -> g_feat16 (B,H,W,C) fp16 (channels contiguous).
// Main: per proposal, stage 32-channel patch tiles into smem via cp.async.16
// (layout [pos][32ch-half], 64B per position, 16B-slot swizzled by (g+pos)&3),
// compute bilinear+pool in fp32 with 8-channels-per-LDS.128, double buffered.

#define BB 4
#define NN 512
#define CC 256
#define HF 50
#define WF 50
#define HW (HF * WF)
#define TCH 32              // channels per tile
#define NT (CC / TCH)       // 8 tiles
#define MAXPOS 484          // max patch positions (22*22)
#define BUFB (MAXPOS * 64)  // bytes per stage buffer (30976)

__device__ __align__(128) __half g_feat16[BB * HW * CC];

// ---------------- prepass: (b,c,hw) f32 -> (b,hw,c) fp16 ----------------
__global__ __launch_bounds__(256)
void transpose_kernel(const float* __restrict__ features)
{
    __shared__ float tile[32][33];
    const int hw0 = blockIdx.x * 32;
    const int c0  = blockIdx.y * 32;
    const int b   = blockIdx.z;
    const int tx = threadIdx.x, ty = threadIdx.y;   // 32 x 8

    const float* src = features + ((long)b * CC + c0) * HW + hw0;
    #pragma unroll
    for (int k = 0; k < 32; k += 8) {
        if (hw0 + tx < HW) tile[ty + k][tx] = src[(long)(ty + k) * HW + tx];
    }
    __syncthreads();
    __half* dst = g_feat16 + ((long)b * HW + hw0) * CC + c0;
    #pragma unroll
    for (int k = 0; k < 32; k += 8) {
        if (hw0 + ty + k < HW) dst[(long)(ty + k) * CC + tx] = __float2half(tile[tx][ty + k]);
    }
}

// ---------------- main kernel ----------------
__device__ __forceinline__ void cp_async16(unsigned saddr, const void* gptr) {
    asm volatile("cp.async.cg.shared.global [%0], [%1], 16;\n"
                 :: "r"(saddr), "l"(gptr));
}

extern __shared__ unsigned char dynsmem[];

__global__ __launch_bounds__(256)
void roi_align_pool_kernel(const float* __restrict__ proposals,
                           float* __restrict__ out)
{
    const int bn = blockIdx.x;
    const int b  = bn >> 9;

    __shared__ int   s_box[4];
    __shared__ int   s_rlh[14], s_rhh[14];   // row low/high * h  (pos = r*h + c)
    __shared__ int   s_cl[14],  s_ch[14];
    __shared__ float s_rf[14],  s_cf[14];

    const int tid = threadIdx.x;

    if (tid < 4) s_box[tid] = (int)(proposals[bn * 4 + tid] * 0.0625f);
    __syncthreads();
    const int x = s_box[0], y = s_box[1], w = s_box[2], h = s_box[3];

    if (tid < 28) {
        const bool  isRow = tid < 14;
        const int   ii    = isRow ? tid : tid - 14;
        const int   len   = isRow ? w : h;
        const float scale = (float)(len - 1) / 13.0f;
        const float c     = (float)ii * scale;
        const int   low   = (int)floorf(c);
        const float frac  = c - (float)low;
        const int   high  = min(low + 1, len - 1);
        if (isRow) { s_rlh[ii] = low * h; s_rhh[ii] = high * h; s_rf[ii] = frac; }
        else       { s_cl[ii]  = low;     s_ch[ii]  = high;     s_cf[ii] = frac; }
    }
    __syncthreads();

    // ---- per-thread compute meta in registers: (g = 8ch group, p = position)
    const bool active = tid < 196;
    const int  g = tid / 49;
    const int  p = tid - g * 49;
    int   off[16];
    float wts[16];
    if (active) {
        const int pi = p / 7;
        const int pj = p - pi * 7;
        #pragma unroll
        for (int dg = 0; dg < 4; dg++) {
            const int i = 2 * pi + (dg >> 1);
            const int j = 2 * pj + (dg & 1);
            const int rlh = s_rlh[i], rhh = s_rhh[i];
            const int cl  = s_cl[j],  chh = s_ch[j];
            const float rf = s_rf[i], cf = s_cf[j];
            const float irf = 1.0f - rf, icf = 1.0f - cf;
            const int pos0 = rlh + cl, pos1 = rlh + chh;
            const int pos2 = rhh + cl, pos3 = rhh + chh;
            off[dg * 4 + 0] = pos0 * 64 + (((g + pos0) & 3) << 4);
            off[dg * 4 + 1] = pos1 * 64 + (((g + pos1) & 3) << 4);
            off[dg * 4 + 2] = pos2 * 64 + (((g + pos2) & 3) << 4);
            off[dg * 4 + 3] = pos3 * 64 + (((g + pos3) & 3) << 4);
            wts[dg * 4 + 0] = irf * icf;
            wts[dg * 4 + 1] = irf * cf;
            wts[dg * 4 + 2] = rf * icf;
            wts[dg * 4 + 3] = rf * cf;
        }
    }

    const unsigned smem_base = (unsigned)__cvta_generic_to_shared(dynsmem);
    const int  h4    = h * 4;
    const int  total = w * h4;
    const __half* const gsrc = g_feat16 + ((long)b * HW) * CC;

    // ---- staging (tile t into buffer bufsel) ----
    auto stage = [&](int t, int bufsel) {
        const unsigned sbase = smem_base + bufsel * BUFB;
        const __half* src0 = gsrc + t * TCH;
        for (int it = tid; it < total; it += 256) {
            const int r     = it / h4;
            const int rem   = it - r * h4;
            const int c     = rem >> 2;
            const int chunk = rem & 3;
            const int pos   = r * h + c;
            const __half* src = src0 + (long)((x + r) * WF + (y + c)) * CC + chunk * 8;
            const unsigned dst = sbase + pos * 64 + (((chunk + pos) & 3) << 4);
            cp_async16(dst, src);
        }
        asm volatile("cp.async.commit_group;\n" ::: "memory");
    };

    stage(0, 0);

    for (int t = 0; t < NT; t++) {
        if (t + 1 < NT) {
            stage(t + 1, (t + 1) & 1);
            asm volatile("cp.async.wait_group 1;\n" ::: "memory");
        } else {
            asm volatile("cp.async.wait_group 0;\n" ::: "memory");
        }
        __syncthreads();

        if (active) {
            const unsigned char* base = dynsmem + (t & 1) * BUFB;
            float2 m0 = make_float2(-INFINITY, -INFINITY);
            float2 m1 = m0, m2 = m0, m3 = m0;
            #pragma unroll
            for (int dg = 0; dg < 4; dg++) {
                float2 s0 = make_float2(0.f, 0.f), s1 = s0, s2 = s0, s3 = s0;
                #pragma unroll
                for (int k = 0; k < 4; k++) {
                    const uint4 q = *(const uint4*)(base + off[dg * 4 + k]);
                    const float wv = wts[dg * 4 + k];
                    const float2 f0 = __half22float2(*(const __half2*)&q.x);
                    const float2 f1 = __half22float2(*(const __half2*)&q.y);
                    const float2 f2 = __half22float2(*(const __half2*)&q.z);
                    const float2 f3 = __half22float2(*(const __half2*)&q.w);
                    s0.x = fmaf(wv, f0.x, s0.x); s0.y = fmaf(wv, f0.y, s0.y);
                    s1.x = fmaf(wv, f1.x, s1.x); s1.y = fmaf(wv, f1.y, s1.y);
                    s2.x = fmaf(wv, f2.x, s2.x); s2.y = fmaf(wv, f2.y, s2.y);
                    s3.x = fmaf(wv, f3.x, s3.x); s3.y = fmaf(wv, f3.y, s3.y);
                }
                m0.x = fmaxf(m0.x, s0.x); m0.y = fmaxf(m0.y, s0.y);
                m1.x = fmaxf(m1.x, s1.x); m1.y = fmaxf(m1.y, s1.y);
                m2.x = fmaxf(m2.x, s2.x); m2.y = fmaxf(m2.y, s2.y);
                m3.x = fmaxf(m3.x, s3.x); m3.y = fmaxf(m3.y, s3.y);
            }
            float* o = out + ((long)bn * CC + t * TCH + g * 8) * 49 + p;
            o[0]       = m0.x;  o[49]      = m0.y;
            o[98]      = m1.x;  o[147]     = m1.y;
            o[196]     = m2.x;  o[245]     = m2.y;
            o[294]     = m3.x;  o[343]     = m3.y;
        }
        __syncthreads();
    }
}

extern "C" void kernel_launch(void* const* d_in, const int* in_sizes, int n_in,
                              void* d_out, int out_size)
{
    const float* proposals = (const float*)d_in[0];   // (B,N,4) f32
    const float* features  = (const float*)d_in[1];   // (B,C,Hf,Wf) f32
    float* out = (float*)d_out;                       // (B,N,C,7,7) f32
    (void)in_sizes; (void)n_in; (void)out_size;

    cudaFuncSetAttribute(roi_align_pool_kernel,
                         cudaFuncAttributeMaxDynamicSharedMemorySize, 2 * BUFB);

    dim3 tgrid((HW + 31) / 32, CC / 32, BB);
    dim3 tblock(32, 8);
    transpose_kernel<<<tgrid, tblock>>>(features);

    roi_align_pool_kernel<<<BB * NN, 256, 2 * BUFB>>>(proposals, out);
}

// round 5
// speedup vs baseline: 6.7945x; 1.5284x over previous
#include <cuda_runtime.h>
#include <cuda_fp16.h>
#include <math.h>

// ROI align (14x14 bilinear) + 2x2 maxpool -> (B,N,C,7,7)
// B=4, N=512, C=256, Hf=Wf=50, fx=fy=0.0625. Box: x,y<=22, w,h in [5,22].
//
// Prepass: features (B,C,H,W) f32 -> g_feat16 (B,H,W,C) fp16 (channels contiguous,
//          512 B per spatial position).
// Main: warp = grid position p (0..48); lane = 8-channel slice. For each of the
// 4 bilinear grid points, load 4 corner texels as coalesced 512B LDG.128 sweeps,
// combine + pool-max in half2, write via smem transpose for coalesced STG.

#define BB 4
#define NN 512
#define CC 256
#define HF 50
#define WF 50
#define HW (HF * WF)
#define OSTRIDE 260          // padded smem row stride (words), mult of 4

__device__ __align__(128) __half g_feat16[BB * HW * CC];

// ---------------- prepass: (b,c,hw) f32 -> (b,hw,c) fp16 ----------------
__global__ __launch_bounds__(256)
void transpose_kernel(const float* __restrict__ features)
{
    __shared__ float tile[32][33];
    const int hw0 = blockIdx.x * 32;
    const int c0  = blockIdx.y * 32;
    const int b   = blockIdx.z;
    const int tx = threadIdx.x, ty = threadIdx.y;   // 32 x 8

    const float* src = features + ((long)b * CC + c0) * HW + hw0;
    #pragma unroll
    for (int k = 0; k < 32; k += 8) {
        if (hw0 + tx < HW) tile[ty + k][tx] = src[(long)(ty + k) * HW + tx];
    }
    __syncthreads();
    __half* dst = g_feat16 + ((long)b * HW + hw0) * CC + c0;
    #pragma unroll
    for (int k = 0; k < 32; k += 8) {
        if (hw0 + ty + k < HW) dst[(long)(ty + k) * CC + tx] = __float2half(tile[tx][ty + k]);
    }
}

// ---------------- main kernel ----------------
extern __shared__ float s_out[];   // [49][OSTRIDE]

__global__ __launch_bounds__(256)
void roi_align_pool_kernel(const float* __restrict__ proposals,
                           float* __restrict__ out)
{
    __shared__ int   s_box[4];
    __shared__ int   s_rl[14], s_rh[14];   // (x + row_low/high) * WF
    __shared__ int   s_cl[14], s_ch[14];   // y + col_low/high
    __shared__ float s_rf[14], s_cf[14];

    const int bn  = blockIdx.x;
    const int b   = bn >> 9;
    const int tid = threadIdx.x;
    const int warp = tid >> 5, lane = tid & 31;

    if (tid < 4) s_box[tid] = (int)(proposals[bn * 4 + tid] * 0.0625f);
    __syncthreads();
    const int x = s_box[0], y = s_box[1], w = s_box[2], h = s_box[3];

    if (tid < 28) {
        const bool  isRow = tid < 14;
        const int   ii    = isRow ? tid : tid - 14;
        const int   len   = isRow ? w : h;
        const float scale = (float)(len - 1) / 13.0f;
        const float c     = (float)ii * scale;
        const int   low   = (int)floorf(c);
        const float frac  = c - (float)low;
        const int   high  = min(low + 1, len - 1);
        if (isRow) { s_rl[ii] = (x + low) * WF; s_rh[ii] = (x + high) * WF; s_rf[ii] = frac; }
        else       { s_cl[ii] = y + low;        s_ch[ii] = y + high;        s_cf[ii] = frac; }
    }
    __syncthreads();

    const __half* __restrict__ img = g_feat16 + (long)b * HW * CC;
    const int lane8 = lane * 8;

    // ---- compute: warp = position, lane = 8-channel slice ----
    for (int p = warp; p < 49; p += 8) {
        const int pi = p / 7;
        const int pj = p - pi * 7;

        __half2 m0, m1, m2, m3;
        #pragma unroll
        for (int dg = 0; dg < 4; dg++) {
            const int i = 2 * pi + (dg >> 1);
            const int j = 2 * pj + (dg & 1);
            const int r0 = s_rl[i], r1 = s_rh[i];
            const int c0 = s_cl[j], c1 = s_ch[j];

            const uint4 q00 = *(const uint4*)(img + (r0 + c0) * CC + lane8);
            const uint4 q01 = *(const uint4*)(img + (r0 + c1) * CC + lane8);
            const uint4 q10 = *(const uint4*)(img + (r1 + c0) * CC + lane8);
            const uint4 q11 = *(const uint4*)(img + (r1 + c1) * CC + lane8);

            const float rf = s_rf[i], cf = s_cf[j];
            const float irf = 1.0f - rf, icf = 1.0f - cf;
            const __half2 W00 = __float2half2_rn(irf * icf);
            const __half2 W01 = __float2half2_rn(irf * cf);
            const __half2 W10 = __float2half2_rn(rf * icf);
            const __half2 W11 = __float2half2_rn(rf * cf);

            const __half2* h00 = (const __half2*)&q00;
            const __half2* h01 = (const __half2*)&q01;
            const __half2* h10 = (const __half2*)&q10;
            const __half2* h11 = (const __half2*)&q11;

            __half2 v0 = __hmul2(W00, h00[0]);
            __half2 v1 = __hmul2(W00, h00[1]);
            __half2 v2 = __hmul2(W00, h00[2]);
            __half2 v3 = __hmul2(W00, h00[3]);
            v0 = __hfma2(W01, h01[0], v0); v1 = __hfma2(W01, h01[1], v1);
            v2 = __hfma2(W01, h01[2], v2); v3 = __hfma2(W01, h01[3], v3);
            v0 = __hfma2(W10, h10[0], v0); v1 = __hfma2(W10, h10[1], v1);
            v2 = __hfma2(W10, h10[2], v2); v3 = __hfma2(W10, h10[3], v3);
            v0 = __hfma2(W11, h11[0], v0); v1 = __hfma2(W11, h11[1], v1);
            v2 = __hfma2(W11, h11[2], v2); v3 = __hfma2(W11, h11[3], v3);

            if (dg == 0) { m0 = v0; m1 = v1; m2 = v2; m3 = v3; }
            else {
                m0 = __hmax2(m0, v0); m1 = __hmax2(m1, v1);
                m2 = __hmax2(m2, v2); m3 = __hmax2(m3, v3);
            }
        }

        const float2 f0 = __half22float2(m0);
        const float2 f1 = __half22float2(m1);
        const float2 f2 = __half22float2(m2);
        const float2 f3 = __half22float2(m3);
        float* dst = s_out + p * OSTRIDE + lane8;
        *(float4*)(dst)     = make_float4(f0.x, f0.y, f1.x, f1.y);
        *(float4*)(dst + 4) = make_float4(f2.x, f2.y, f3.x, f3.y);
    }
    __syncthreads();

    // ---- writeout: coalesced STG, incremental (c,p) from linear idx ----
    const long obase = (long)bn * (CC * 49);
    int c = tid / 49;
    int p = tid - c * 49;
    for (int idx = tid; idx < CC * 49; idx += 256) {
        out[obase + idx] = s_out[p * OSTRIDE + c];
        p += 11; c += 5;              // 256 = 5*49 + 11
        if (p >= 49) { p -= 49; c += 1; }
    }
}

extern "C" void kernel_launch(void* const* d_in, const int* in_sizes, int n_in,
                              void* d_out, int out_size)
{
    const float* proposals = (const float*)d_in[0];   // (B,N,4) f32
    const float* features  = (const float*)d_in[1];   // (B,C,Hf,Wf) f32
    float* out = (float*)d_out;                       // (B,N,C,7,7) f32
    (void)in_sizes; (void)n_in; (void)out_size;

    const int smem_bytes = 49 * OSTRIDE * sizeof(float);   // 50960
    cudaFuncSetAttribute(roi_align_pool_kernel,
                         cudaFuncAttributeMaxDynamicSharedMemorySize, smem_bytes);

    dim3 tgrid((HW + 31) / 32, CC / 32, BB);
    dim3 tblock(32, 8);
    transpose_kernel<<<tgrid, tblock>>>(features);

    roi_align_pool_kernel<<<BB * NN, 256, smem_bytes>>>(proposals, out);
}

// round 6
// speedup vs baseline: 7.4598x; 1.0979x over previous
#include <cuda_runtime.h>
#include <cuda_fp16.h>
#include <math.h>

// ROI align (14x14 bilinear) + 2x2 maxpool -> (B,N,C,7,7)
// B=4, N=512, C=256, Hf=Wf=50, fx=fy=0.0625. Box: x,y<=22, w,h in [5,22].
//
// Prepass: features (B,C,H,W) f32 -> g_feat16 (B,H,W,C) fp16 (channels contiguous,
//          512 B per spatial position), half2-vectorized stores.
// Main: warp = grid position p (0..48); lane = 8-channel slice. For each of the
// 4 bilinear grid points, load 4 corner texels as coalesced 512B LDG.128 sweeps,
// combine + pool-max in half2, transpose through fp16 smem for coalesced STG.

#define BB 4
#define NN 512
#define CC 256
#define HF 50
#define WF 50
#define HW (HF * WF)
#define OSH 258              // s_out row stride in halves (516 B = 129 words, odd)

__device__ __align__(128) __half g_feat16[BB * HW * CC];

// ---------------- prepass: (b,c,hw) f32 -> (b,hw,c) fp16 ----------------
__global__ __launch_bounds__(256)
void transpose_kernel(const float* __restrict__ features)
{
    __shared__ __half tile[64][33];
    const int hw0 = blockIdx.x * 32;
    const int c0  = blockIdx.y * 64;
    const int b   = blockIdx.z;
    const int tx = threadIdx.x, ty = threadIdx.y;   // 32 x 8

    const float* src = features + ((long)b * CC + c0) * HW + hw0;
    const bool inb = (hw0 + tx) < HW;
    #pragma unroll
    for (int k = 0; k < 64; k += 8) {
        if (inb) tile[ty + k][tx] = __float2half(src[(long)(ty + k) * HW + tx]);
    }
    __syncthreads();

    __half* dst = g_feat16 + ((long)b * HW + hw0) * CC + c0;
    #pragma unroll
    for (int k = 0; k < 32; k += 8) {
        const int hw = ty + k;
        if (hw0 + hw < HW) {
            __half2 v;
            v.x = tile[2 * tx][hw];
            v.y = tile[2 * tx + 1][hw];
            *(__half2*)(dst + (long)hw * CC + 2 * tx) = v;
        }
    }
}

// ---------------- main kernel ----------------
__global__ __launch_bounds__(256, 6)
void roi_align_pool_kernel(const float* __restrict__ proposals,
                           float* __restrict__ out)
{
    __shared__ int    s_box[4];
    __shared__ int    s_rl[14], s_rh[14];   // (x + row_low/high) * WF
    __shared__ int    s_cl[14], s_ch[14];   // y + col_low/high
    __shared__ float  s_rf[14], s_cf[14];
    __shared__ __half s_out[49 * OSH];      // [p][c], 25.3 KB

    const int bn  = blockIdx.x;
    const int b   = bn >> 9;
    const int tid = threadIdx.x;
    const int warp = tid >> 5, lane = tid & 31;

    if (tid < 4) s_box[tid] = (int)(proposals[bn * 4 + tid] * 0.0625f);
    __syncthreads();
    const int x = s_box[0], y = s_box[1], w = s_box[2], h = s_box[3];

    if (tid < 28) {
        const bool  isRow = tid < 14;
        const int   ii    = isRow ? tid : tid - 14;
        const int   len   = isRow ? w : h;
        const float scale = (float)(len - 1) / 13.0f;
        const float c     = (float)ii * scale;
        const int   low   = (int)floorf(c);
        const float frac  = c - (float)low;
        const int   high  = min(low + 1, len - 1);
        if (isRow) { s_rl[ii] = (x + low) * WF; s_rh[ii] = (x + high) * WF; s_rf[ii] = frac; }
        else       { s_cl[ii] = y + low;        s_ch[ii] = y + high;        s_cf[ii] = frac; }
    }
    __syncthreads();

    const __half* __restrict__ img = g_feat16 + (long)b * HW * CC;
    const int lane8 = lane * 8;

    // ---- compute: warp = position, lane = 8-channel slice ----
    for (int p = warp; p < 49; p += 8) {
        const int pi = p / 7;
        const int pj = p - pi * 7;

        __half2 m0, m1, m2, m3;
        #pragma unroll
        for (int dg = 0; dg < 4; dg++) {
            const int i = 2 * pi + (dg >> 1);
            const int j = 2 * pj + (dg & 1);
            const int r0 = s_rl[i], r1 = s_rh[i];
            const int c0 = s_cl[j], c1 = s_ch[j];

            const uint4 q00 = *(const uint4*)(img + (r0 + c0) * CC + lane8);
            const uint4 q01 = *(const uint4*)(img + (r0 + c1) * CC + lane8);
            const uint4 q10 = *(const uint4*)(img + (r1 + c0) * CC + lane8);
            const uint4 q11 = *(const uint4*)(img + (r1 + c1) * CC + lane8);

            const float rf = s_rf[i], cf = s_cf[j];
            const float irf = 1.0f - rf, icf = 1.0f - cf;
            const __half2 W00 = __float2half2_rn(irf * icf);
            const __half2 W01 = __float2half2_rn(irf * cf);
            const __half2 W10 = __float2half2_rn(rf * icf);
            const __half2 W11 = __float2half2_rn(rf * cf);

            const __half2* h00 = (const __half2*)&q00;
            const __half2* h01 = (const __half2*)&q01;
            const __half2* h10 = (const __half2*)&q10;
            const __half2* h11 = (const __half2*)&q11;

            __half2 v0 = __hmul2(W00, h00[0]);
            __half2 v1 = __hmul2(W00, h00[1]);
            __half2 v2 = __hmul2(W00, h00[2]);
            __half2 v3 = __hmul2(W00, h00[3]);
            v0 = __hfma2(W01, h01[0], v0); v1 = __hfma2(W01, h01[1], v1);
            v2 = __hfma2(W01, h01[2], v2); v3 = __hfma2(W01, h01[3], v3);
            v0 = __hfma2(W10, h10[0], v0); v1 = __hfma2(W10, h10[1], v1);
            v2 = __hfma2(W10, h10[2], v2); v3 = __hfma2(W10, h10[3], v3);
            v0 = __hfma2(W11, h11[0], v0); v1 = __hfma2(W11, h11[1], v1);
            v2 = __hfma2(W11, h11[2], v2); v3 = __hfma2(W11, h11[3], v3);

            if (dg == 0) { m0 = v0; m1 = v1; m2 = v2; m3 = v3; }
            else {
                m0 = __hmax2(m0, v0); m1 = __hmax2(m1, v1);
                m2 = __hmax2(m2, v2); m3 = __hmax2(m3, v3);
            }
        }

        // STS.128: 8 halves per lane, consecutive lanes contiguous -> conflict-free
        __half2* dst = (__half2*)(s_out + p * OSH + lane8);
        dst[0] = m0; dst[1] = m1; dst[2] = m2; dst[3] = m3;
    }
    __syncthreads();

    // ---- writeout: coalesced STG.32; consecutive tid -> stride 129 words in smem
    const long obase = (long)bn * (CC * 49);
    int c = tid / 49;
    int p = tid - c * 49;
    for (int idx = tid; idx < CC * 49; idx += 256) {
        out[obase + idx] = __half2float(s_out[p * OSH + c]);
        p += 11; c += 5;              // 256 = 5*49 + 11
        if (p >= 49) { p -= 49; c += 1; }
    }
}

extern "C" void kernel_launch(void* const* d_in, const int* in_sizes, int n_in,
                              void* d_out, int out_size)
{
    const float* proposals = (const float*)d_in[0];   // (B,N,4) f32
    const float* features  = (const float*)d_in[1];   // (B,C,Hf,Wf) f32
    float* out = (float*)d_out;                       // (B,N,C,7,7) f32
    (void)in_sizes; (void)n_in; (void)out_size;

    dim3 tgrid((HW + 31) / 32, CC / 64, BB);
    dim3 tblock(32, 8);
    transpose_kernel<<<tgrid, tblock>>>(features);

    roi_align_pool_kernel<<<BB * NN, 256>>>(proposals, out);
}